// round 9
// baseline (speedup 1.0000x reference)
#include <cuda_runtime.h>
#include <math.h>
#include <float.h>

// ---------------------------------------------------------------------------
// EceLabelShift: equal-mass-bin ECE with label-shift weighting.
//   conf = max softmax prob  (= 1/sum(exp(l - max)))
//   edges = equal-mass quantiles of conf_target (exact order statistics via
//           2-level radix histogram on the positive-float bit pattern)
//   per-bin: weighted source accuracy -> cond_expect; sum (conf_t - ce)^2
// ---------------------------------------------------------------------------

#define NC      100
#define NBINS   15
#define HSIZE   (1 << 18)            // conf in (0,1] -> bits>>12 < 0x40000
#define CHUNK   1024
#define NCHUNK  (HSIZE / CHUNK)      // 256
#define NRANK   32                   // 16 edges x (i, i+1) rank pairs
#define NMAX    500000

struct ZeroBlock {
    unsigned hist[HSIZE];
    unsigned subhist[NRANK * 4096];
    double   wnum[NBINS];
    double   total;
    unsigned cnt[NBINS];
};
__device__ ZeroBlock gz;

__device__ float    g_conf_t[NMAX];
__device__ float    g_conf_s[NMAX];
__device__ float    g_wper[NMAX];
__device__ int      g_rankBin[NRANK];
__device__ unsigned g_rankBase[NRANK];
__device__ float    g_edges[16];
__device__ float    g_ce[NBINS];
__device__ unsigned char g_cntok[NBINS];
__device__ int      g_lab64;

// rank (0-indexed order statistic) needed for edge k: pair (i, i+1), clamped.
__device__ __forceinline__ long long rank_for(int t, int nt) {
    int k = t >> 1;
    double xq = (double)k * (double)nt / 15.0;
    long long i = (long long)floor(xq);
    if (i > (long long)nt - 1) i = (long long)nt - 1;
    long long r = i + (t & 1);
    if (r > (long long)nt - 1) r = (long long)nt - 1;
    return r;
}

// Detect labels dtype: int64 => odd 32-bit words of first 64 entries are 0.
__global__ void k_detect(const unsigned* __restrict__ lab) {
    if (threadIdx.x == 0 && blockIdx.x == 0) {
        int is64 = 1;
        for (int i = 0; i < 64; i++)
            if (lab[2 * i + 1] != 0u) { is64 = 0; break; }
        g_lab64 = is64;
    }
}

// One warp per row: conf_t + 2^18-bin histogram of float bit pattern.
__global__ void k_conf_t(const float* __restrict__ lg, int n) {
    int gw   = (blockIdx.x * blockDim.x + threadIdx.x) >> 5;
    int lane = threadIdx.x & 31;
    if (gw >= n) return;
    const float* p = lg + (size_t)gw * NC;
    float v0 = p[lane], v1 = p[lane + 32], v2 = p[lane + 64];
    float v3 = (lane < 4) ? p[96 + lane] : -FLT_MAX;
    float m = fmaxf(fmaxf(v0, v1), fmaxf(v2, v3));
#pragma unroll
    for (int o = 16; o; o >>= 1) m = fmaxf(m, __shfl_xor_sync(0xffffffffu, m, o));
    float s = __expf(v0 - m) + __expf(v1 - m) + __expf(v2 - m);
    if (lane < 4) s += __expf(v3 - m);
#pragma unroll
    for (int o = 16; o; o >>= 1) s += __shfl_xor_sync(0xffffffffu, s, o);
    if (lane == 0) {
        float c = 1.0f / s;
        g_conf_t[gw] = c;
        atomicAdd(&gz.hist[__float_as_uint(c) >> 12], 1u);
    }
}

// One warp per row: conf_s, argmax (first-index ties), w_per = weight[lab]*acc.
__global__ void k_conf_s(const float* __restrict__ lg, const void* __restrict__ labels,
                         const float* __restrict__ wt, int n) {
    int gw   = (blockIdx.x * blockDim.x + threadIdx.x) >> 5;
    int lane = threadIdx.x & 31;
    if (gw >= n) return;
    const float* p = lg + (size_t)gw * NC;
    float v0 = p[lane], v1 = p[lane + 32], v2 = p[lane + 64];
    float v3 = (lane < 4) ? p[96 + lane] : -FLT_MAX;
    float bv = v0; int bi = lane;
    if (v1 > bv) { bv = v1; bi = lane + 32; }
    if (v2 > bv) { bv = v2; bi = lane + 64; }
    if (lane < 4 && v3 > bv) { bv = v3; bi = lane + 96; }
#pragma unroll
    for (int o = 16; o; o >>= 1) {
        float ov = __shfl_xor_sync(0xffffffffu, bv, o);
        int   oi = __shfl_xor_sync(0xffffffffu, bi, o);
        if (ov > bv || (ov == bv && oi < bi)) { bv = ov; bi = oi; }
    }
    float m = bv;
    float s = __expf(v0 - m) + __expf(v1 - m) + __expf(v2 - m);
    if (lane < 4) s += __expf(v3 - m);
#pragma unroll
    for (int o = 16; o; o >>= 1) s += __shfl_xor_sync(0xffffffffu, s, o);
    if (lane == 0) {
        g_conf_s[gw] = 1.0f / s;
        long long lab;
        if (g_lab64) lab = ((const long long*)labels)[gw];
        else         lab = (long long)((const int*)labels)[gw];
        g_wper[gw] = (bi == (int)lab) ? wt[lab] : 0.0f;
    }
}

// Single block (1024 thr): chunk sums + prefix, then warp-per-rank coarse bin.
__global__ void k_locate(int nt) {
    __shared__ unsigned csum[NCHUNK];
    __shared__ unsigned cpref[NCHUNK + 1];
    int tid = threadIdx.x, warp = tid >> 5, lane = tid & 31;
    for (int c = warp; c < NCHUNK; c += 32) {
        unsigned s = 0;
        for (int j = lane; j < CHUNK; j += 32) s += gz.hist[c * CHUNK + j];
#pragma unroll
        for (int o = 16; o; o >>= 1) s += __shfl_xor_sync(0xffffffffu, s, o);
        if (lane == 0) csum[c] = s;
    }
    __syncthreads();
    if (tid == 0) {
        unsigned acc = 0;
        for (int c = 0; c < NCHUNK; c++) { cpref[c] = acc; acc += csum[c]; }
        cpref[NCHUNK] = acc;
    }
    __syncthreads();
    long long r = rank_for(warp, nt);
    int c = 0;
    if (lane == 0) { while (c < NCHUNK - 1 && (long long)cpref[c + 1] <= r) c++; }
    c = __shfl_sync(0xffffffffu, c, 0);
    unsigned cum = cpref[c];
    for (int base = 0; base < CHUNK; base += 32) {
        unsigned h = gz.hist[c * CHUNK + base + lane];
        unsigned sc = h;
#pragma unroll
        for (int o = 1; o < 32; o <<= 1) {
            unsigned u = __shfl_up_sync(0xffffffffu, sc, o);
            if (lane >= o) sc += u;
        }
        unsigned tot = __shfl_sync(0xffffffffu, sc, 31);
        if ((long long)cum + tot > r) {
            unsigned mask = __ballot_sync(0xffffffffu, (long long)cum + sc > r);
            int l = __ffs(mask) - 1;
            if (lane == l) {
                g_rankBin[warp]  = c * CHUNK + base + lane;
                g_rankBase[warp] = cum + sc - h;
            }
            break;
        }
        cum += tot;
    }
}

// Sub-histogram (low 12 key bits) for each rank's coarse bin.
__global__ void k_refine(int nt) {
    __shared__ int sb[NRANK];
    if (threadIdx.x < NRANK) sb[threadIdx.x] = g_rankBin[threadIdx.x];
    __syncthreads();
    int stride = gridDim.x * blockDim.x;
    for (int i = blockIdx.x * blockDim.x + threadIdx.x; i < nt; i += stride) {
        unsigned key = __float_as_uint(g_conf_t[i]);
        int b = (int)(key >> 12);
        unsigned low = key & 4095u;
#pragma unroll
        for (int t = 0; t < NRANK; t++)
            if (sb[t] == b) atomicAdd(&gz.subhist[t * 4096 + low], 1u);
    }
}

// Warp-per-rank scan of sub-histograms -> exact order-stat floats -> edges.
__global__ void k_select(int nt) {
    __shared__ float srt[NRANK];
    int tid = threadIdx.x, warp = tid >> 5, lane = tid & 31;
    long long target = rank_for(warp, nt) - (long long)g_rankBase[warp];
    int binhi = g_rankBin[warp];
    unsigned cum = 0;
    for (int base = 0; base < 4096; base += 32) {
        unsigned h = gz.subhist[warp * 4096 + base + lane];
        unsigned sc = h;
#pragma unroll
        for (int o = 1; o < 32; o <<= 1) {
            unsigned u = __shfl_up_sync(0xffffffffu, sc, o);
            if (lane >= o) sc += u;
        }
        unsigned tot = __shfl_sync(0xffffffffu, sc, 31);
        if ((long long)cum + tot > target) {
            unsigned mask = __ballot_sync(0xffffffffu, (long long)cum + sc > target);
            int l = __ffs(mask) - 1;
            if (lane == l)
                srt[warp] = __uint_as_float(((unsigned)binhi << 12) | (unsigned)(base + lane));
            break;
        }
        cum += tot;
    }
    __syncthreads();
    if (tid < 16) {
        int k = tid; float e;
        if (k == 0)       e = srt[0];
        else if (k == 15) e = srt[31];
        else {
            double xq = (double)k * (double)nt / 15.0;
            long long i = (long long)floor(xq);
            double frac = xq - (double)i;
            double a = srt[2 * k], b2 = srt[2 * k + 1];
            e = (float)(a + frac * (b2 - a));
        }
        g_edges[k] = e;
    }
}

// Bin accumulation: blocks [0,srcBlocks) -> weighted_num, rest -> count_t.
__global__ void k_binacc(int ns, int nt, int srcBlocks) {
    __shared__ float    se[16];
    __shared__ float    swn[NBINS];
    __shared__ unsigned sct[NBINS];
    int tid = threadIdx.x;
    if (tid < 16)    se[tid] = g_edges[tid];
    if (tid < NBINS) { swn[tid] = 0.0f; sct[tid] = 0u; }
    __syncthreads();
    if ((int)blockIdx.x < srcBlocks) {
        int stride = srcBlocks * blockDim.x;
        for (int i = blockIdx.x * blockDim.x + tid; i < ns; i += stride) {
            float w = g_wper[i];
            if (w != 0.0f) {
                float c = g_conf_s[i];
                if (c > se[0] && c <= se[15]) {
#pragma unroll
                    for (int b = 0; b < NBINS; b++)
                        if (c <= se[b + 1]) { atomicAdd(&swn[b], w); break; }
                }
            }
        }
    } else {
        int nb = gridDim.x - srcBlocks;
        int stride = nb * blockDim.x;
        for (int i = ((int)blockIdx.x - srcBlocks) * blockDim.x + tid; i < nt; i += stride) {
            float c = g_conf_t[i];
            if (c > se[0] && c <= se[15]) {
#pragma unroll
                for (int b = 0; b < NBINS; b++)
                    if (c <= se[b + 1]) { atomicAdd(&sct[b], 1u); break; }
            }
        }
    }
    __syncthreads();
    if (tid < NBINS) {
        if (swn[tid] != 0.0f) atomicAdd(&gz.wnum[tid], (double)swn[tid]);
        if (sct[tid])         atomicAdd(&gz.cnt[tid], sct[tid]);
    }
}

__global__ void k_ce(int ns, int nt) {
    int b = threadIdx.x;
    if (b < NBINS) {
        long long ct = (long long)gz.cnt[b];
        long long d  = ct - 1; if (d < 1) d = 1;
        double normal = (double)(nt - 1) / (double)ns;
        g_ce[b]    = (float)(normal * gz.wnum[b] / (double)d);
        g_cntok[b] = (ct > 1) ? 1 : 0;
    }
}

// Sum of (conf_t - cond_expect[bin])^2 over binned target samples.
__global__ void k_diff(int nt) {
    __shared__ float         se[16];
    __shared__ float         sce[NBINS];
    __shared__ unsigned char sok[NBINS];
    int tid = threadIdx.x;
    if (tid < 16)    se[tid] = g_edges[tid];
    if (tid < NBINS) { sce[tid] = g_ce[tid]; sok[tid] = g_cntok[tid]; }
    __syncthreads();
    double local = 0.0;
    int stride = gridDim.x * blockDim.x;
    for (int i = blockIdx.x * blockDim.x + tid; i < nt; i += stride) {
        float c = g_conf_t[i];
        if (c > se[0] && c <= se[15]) {
#pragma unroll
            for (int b = 0; b < NBINS; b++)
                if (c <= se[b + 1]) {
                    if (sok[b]) { float d = c - sce[b]; local += (double)d * (double)d; }
                    break;
                }
        }
    }
#pragma unroll
    for (int o = 16; o; o >>= 1) local += __shfl_down_sync(0xffffffffu, local, o);
    __shared__ double warpsum[8];
    if ((tid & 31) == 0) warpsum[tid >> 5] = local;
    __syncthreads();
    if (tid < 8) {
        double v = warpsum[tid];
#pragma unroll
        for (int o = 4; o; o >>= 1) v += __shfl_down_sync(0xffu, v, o);
        if (tid == 0) atomicAdd(&gz.total, v);
    }
}

__global__ void k_final(float* out, int nt) {
    out[0] = (float)(gz.total / (double)nt);
}

extern "C" void kernel_launch(void* const* d_in, const int* in_sizes, int n_in,
                              void* d_out, int out_size) {
    const float* lg_s = (const float*)d_in[0];
    const void*  lab  = d_in[1];
    const float* lg_t = (const float*)d_in[2];
    const float* wt   = (const float*)d_in[3];
    int ns = in_sizes[0] / NC;
    int nt = in_sizes[2] / NC;

    void* zp = nullptr;
    cudaGetSymbolAddress(&zp, gz);
    cudaMemsetAsync(zp, 0, sizeof(ZeroBlock), 0);

    k_detect<<<1, 32>>>((const unsigned*)lab);

    const int WPB = 8;  // warps per 256-thread block, one warp per row
    int blocks_t = (nt + WPB - 1) / WPB;
    int blocks_s = (ns + WPB - 1) / WPB;
    k_conf_t<<<blocks_t, 256>>>(lg_t, nt);
    k_conf_s<<<blocks_s, 256>>>(lg_s, lab, wt, ns);

    k_locate<<<1, 1024>>>(nt);
    k_refine<<<592, 256>>>(nt);
    k_select<<<1, 1024>>>(nt);
    k_binacc<<<1024, 256>>>(ns, nt, 512);
    k_ce<<<1, 32>>>(ns, nt);
    k_diff<<<592, 256>>>(nt);
    k_final<<<1, 1>>>((float*)d_out, nt);
    (void)n_in; (void)out_size;
}

// round 10
// speedup vs baseline: 1.3769x; 1.3769x over previous
#include <cuda_runtime.h>
#include <math.h>
#include <float.h>

// ---------------------------------------------------------------------------
// EceLabelShift: equal-mass-bin ECE with label-shift weighting.
//   conf = max softmax prob  (= 1/sum(exp(l - max)))
//   edges = equal-mass quantiles of conf_target (exact order statistics via
//           2-level radix histogram on the positive-float bit pattern)
//   per-bin: weighted source accuracy -> cond_expect; sum (conf_t - ce)^2
// R9: parallelized rank/select (block scans), parallel detect, fused +
//     vectorized softmax pass (float4 + ballot argmax).
// ---------------------------------------------------------------------------

#define NC      100
#define NBINS   15
#define HSIZE   (1 << 18)            // conf in (0,1] -> bits>>12 < 0x40000
#define CHUNK   1024
#define NCHUNK  (HSIZE / CHUNK)      // 256
#define NRANK   32                   // 16 edges x (i, i+1) rank pairs
#define NMAX    500000

struct ZeroBlock {
    unsigned hist[HSIZE];
    unsigned subhist[NRANK * 4096];
    double   wnum[NBINS];
    double   total;
    unsigned cnt[NBINS];
};
__device__ ZeroBlock gz;

__device__ float    g_conf_t[NMAX];
__device__ float    g_conf_s[NMAX];
__device__ float    g_wper[NMAX];
__device__ unsigned g_csum[NCHUNK];
__device__ int      g_rankBin[NRANK];
__device__ unsigned g_rankBase[NRANK];
__device__ float    g_srt[NRANK];
__device__ float    g_edges[16];
__device__ float    g_ce[NBINS];
__device__ unsigned char g_cntok[NBINS];
__device__ int      g_lab64;

// rank (0-indexed order statistic) needed for edge pair t: (i, i+1), clamped.
__device__ __forceinline__ long long rank_for(int t, int nt) {
    int k = t >> 1;
    double xq = (double)k * (double)nt / 15.0;
    long long i = (long long)floor(xq);
    if (i > (long long)nt - 1) i = (long long)nt - 1;
    long long r = i + (t & 1);
    if (r > (long long)nt - 1) r = (long long)nt - 1;
    return r;
}

// Block-wide (1024 thr = 32 warps) inclusive scan of one unsigned per thread.
__device__ __forceinline__ unsigned blockScanIncl(unsigned v, unsigned* sh) {
    int tid = threadIdx.x, lane = tid & 31, w = tid >> 5;
    unsigned sc = v;
#pragma unroll
    for (int o = 1; o < 32; o <<= 1) {
        unsigned u = __shfl_up_sync(0xffffffffu, sc, o);
        if (lane >= o) sc += u;
    }
    if (lane == 31) sh[w] = sc;
    __syncthreads();
    if (w == 0) {
        unsigned t = sh[lane];
#pragma unroll
        for (int o = 1; o < 32; o <<= 1) {
            unsigned u = __shfl_up_sync(0xffffffffu, t, o);
            if (lane >= o) t += u;
        }
        sh[lane] = t;
    }
    __syncthreads();
    unsigned off = w ? sh[w - 1] : 0u;
    return sc + off;
}

// Detect labels dtype: int64 => odd 32-bit words of first 64 entries are 0.
__global__ void k_detect(const unsigned* __restrict__ lab) {
    int t = threadIdx.x;                       // 32 threads
    unsigned v = lab[2 * t + 1] | lab[2 * t + 65];
    unsigned mask = __ballot_sync(0xffffffffu, v != 0u);
    if (t == 0) g_lab64 = (mask == 0u) ? 1 : 0;
}

// Fused conf pass: one warp per row for target (rows [0,nt)) and source rows.
__global__ void k_conf(const float* __restrict__ lg_t, const float* __restrict__ lg_s,
                       const void* __restrict__ labels, const float* __restrict__ wt,
                       int nt, int ns) {
    int gw   = (blockIdx.x * blockDim.x + threadIdx.x) >> 5;
    int lane = threadIdx.x & 31;
    if (gw >= nt + ns) return;
    bool isT = gw < nt;
    int row  = isT ? gw : gw - nt;
    const float* base = isT ? lg_t : lg_s;
    const float4* p = (const float4*)(base + (size_t)row * NC);  // 400B rows: 16B aligned
    float4 v;
    if (lane < 25) v = p[lane];
    else           v = make_float4(-FLT_MAX, -FLT_MAX, -FLT_MAX, -FLT_MAX);

    float m = fmaxf(fmaxf(v.x, v.y), fmaxf(v.z, v.w));
#pragma unroll
    for (int o = 16; o; o >>= 1) m = fmaxf(m, __shfl_xor_sync(0xffffffffu, m, o));

    float s = 0.0f;
    if (lane < 25)
        s = __expf(v.x - m) + __expf(v.y - m) + __expf(v.z - m) + __expf(v.w - m);
#pragma unroll
    for (int o = 16; o; o >>= 1) s += __shfl_xor_sync(0xffffffffu, s, o);

    if (isT) {
        if (lane == 0) {
            float c = 1.0f / s;
            g_conf_t[row] = c;
            atomicAdd(&gz.hist[__float_as_uint(c) >> 12], 1u);
        }
    } else {
        // argmax (first occurrence): find smallest index whose value == m
        int loc = 127;
        if (lane < 25) {
            if (v.w == m) loc = 4 * lane + 3;
            if (v.z == m) loc = 4 * lane + 2;
            if (v.y == m) loc = 4 * lane + 1;
            if (v.x == m) loc = 4 * lane;
        }
        unsigned mask = __ballot_sync(0xffffffffu, loc < 127);
        int src = __ffs(mask) - 1;
        int bi  = __shfl_sync(0xffffffffu, loc, src);
        if (lane == 0) {
            g_conf_s[row] = 1.0f / s;
            long long lab = g_lab64 ? ((const long long*)labels)[row]
                                    : (long long)((const int*)labels)[row];
            g_wper[row] = (bi == (int)lab) ? wt[lab] : 0.0f;
        }
    }
}

// Per-chunk sums of the coarse histogram (grid = NCHUNK blocks).
__global__ void k_csum() {
    int c = blockIdx.x, tid = threadIdx.x;   // 256 threads
    unsigned s = 0;
#pragma unroll
    for (int j = 0; j < CHUNK / 256; j++) s += gz.hist[c * CHUNK + j * 256 + tid];
#pragma unroll
    for (int o = 16; o; o >>= 1) s += __shfl_xor_sync(0xffffffffu, s, o);
    __shared__ unsigned ws[8];
    if ((tid & 31) == 0) ws[tid >> 5] = s;
    __syncthreads();
    if (tid < 8) {
        unsigned v = ws[tid];
#pragma unroll
        for (int o = 4; o; o >>= 1) v += __shfl_xor_sync(0xffu, v, o);
        if (tid == 0) g_csum[c] = v;
    }
}

// One block per rank: prefix over chunk sums, locate chunk, block-scan chunk.
__global__ void k_rank(int nt) {
    __shared__ unsigned cpref[NCHUNK + 1];
    __shared__ unsigned sh[32];
    __shared__ int cIdx;
    __shared__ int firstIdx;
    int tid = threadIdx.x, b = blockIdx.x;
    if (tid == 0) firstIdx = 1 << 30;
    if (tid < 32) {
        unsigned s[8]; unsigned run = 0;
#pragma unroll
        for (int j = 0; j < 8; j++) { unsigned h = g_csum[tid * 8 + j]; s[j] = run; run += h; }
        unsigned sc = run;
#pragma unroll
        for (int o = 1; o < 32; o <<= 1) {
            unsigned u = __shfl_up_sync(0xffffffffu, sc, o);
            if (tid >= o) sc += u;
        }
        unsigned excl = sc - run;
#pragma unroll
        for (int j = 0; j < 8; j++) cpref[tid * 8 + j] = excl + s[j];
        if (tid == 31) cpref[NCHUNK] = excl + run;
    }
    __syncthreads();
    unsigned r = (unsigned)rank_for(b, nt);
    if (tid < NCHUNK && cpref[tid] <= r && r < cpref[tid + 1]) cIdx = tid;
    __syncthreads();
    int c = cIdx;
    unsigned h = gz.hist[c * CHUNK + tid];
    unsigned incl = blockScanIncl(h, sh);
    unsigned cum0 = cpref[c];
    if (cum0 + incl > r) atomicMin(&firstIdx, tid);
    __syncthreads();
    if (tid == firstIdx) {
        g_rankBin[b]  = c * CHUNK + tid;
        g_rankBase[b] = cum0 + incl - h;
    }
}

// Sub-histogram (low 12 key bits) for each rank's coarse bin.
__global__ void k_refine(int nt) {
    __shared__ int sb[NRANK];
    if (threadIdx.x < NRANK) sb[threadIdx.x] = g_rankBin[threadIdx.x];
    __syncthreads();
    int myb[NRANK];
    int bmin = 0x7fffffff, bmax = -1;
#pragma unroll
    for (int t = 0; t < NRANK; t++) {
        myb[t] = sb[t];
        bmin = min(bmin, myb[t]); bmax = max(bmax, myb[t]);
    }
    int stride = gridDim.x * blockDim.x;
    for (int i = blockIdx.x * blockDim.x + threadIdx.x; i < nt; i += stride) {
        unsigned key = __float_as_uint(g_conf_t[i]);
        int bbin = (int)(key >> 12);
        if (bbin < bmin || bbin > bmax) continue;
        unsigned low = key & 4095u;
#pragma unroll
        for (int t = 0; t < NRANK; t++)
            if (myb[t] == bbin) atomicAdd(&gz.subhist[t * 4096 + low], 1u);
    }
}

// One block per rank: block scan of its 4096-bin sub-hist -> exact float.
__global__ void k_select(int nt) {
    __shared__ unsigned sh[32];
    __shared__ int firstIdx;
    int tid = threadIdx.x, b = blockIdx.x;
    if (tid == 0) firstIdx = 1 << 30;
    unsigned target = (unsigned)(rank_for(b, nt) - (long long)g_rankBase[b]);
    unsigned h[4]; unsigned tsum = 0;
    int base = b * 4096 + tid * 4;
#pragma unroll
    for (int j = 0; j < 4; j++) { h[j] = gz.subhist[base + j]; tsum += h[j]; }
    unsigned incl = blockScanIncl(tsum, sh);
    unsigned cum  = incl - tsum;
    int found = -1;
#pragma unroll
    for (int j = 0; j < 4; j++) {
        if (found < 0 && cum + h[j] > target) found = tid * 4 + j;
        cum += h[j];
    }
    if (found >= 0) atomicMin(&firstIdx, found);
    __syncthreads();
    if (tid == 0)
        g_srt[b] = __uint_as_float(((unsigned)g_rankBin[b] << 12) | (unsigned)firstIdx);
}

// Interpolate the 16 equal-mass edges from the 32 order statistics.
__global__ void k_edges(int nt) {
    int k = threadIdx.x;
    if (k < 16) {
        float e;
        if (k == 0)       e = g_srt[0];
        else if (k == 15) e = g_srt[31];
        else {
            double xq = (double)k * (double)nt / 15.0;
            long long i = (long long)floor(xq);
            double frac = xq - (double)i;
            double a = g_srt[2 * k], b2 = g_srt[2 * k + 1];
            e = (float)(a + frac * (b2 - a));
        }
        g_edges[k] = e;
    }
}

// Bin accumulation: blocks [0,srcBlocks) -> weighted_num, rest -> count_t.
__global__ void k_binacc(int ns, int nt, int srcBlocks) {
    __shared__ float    swn[NBINS];
    __shared__ unsigned sct[NBINS];
    int tid = threadIdx.x;
    if (tid < NBINS) { swn[tid] = 0.0f; sct[tid] = 0u; }
    float e[16];
#pragma unroll
    for (int k = 0; k < 16; k++) e[k] = g_edges[k];
    __syncthreads();
    if ((int)blockIdx.x < srcBlocks) {
        int stride = srcBlocks * blockDim.x;
        for (int i = blockIdx.x * blockDim.x + tid; i < ns; i += stride) {
            float w = g_wper[i];
            if (w != 0.0f) {
                float c = g_conf_s[i];
                if (c > e[0] && c <= e[15]) {
#pragma unroll
                    for (int b = 0; b < NBINS; b++)
                        if (c <= e[b + 1]) { atomicAdd(&swn[b], w); break; }
                }
            }
        }
    } else {
        int nb = gridDim.x - srcBlocks;
        int stride = nb * blockDim.x;
        for (int i = ((int)blockIdx.x - srcBlocks) * blockDim.x + tid; i < nt; i += stride) {
            float c = g_conf_t[i];
            if (c > e[0] && c <= e[15]) {
#pragma unroll
                for (int b = 0; b < NBINS; b++)
                    if (c <= e[b + 1]) { atomicAdd(&sct[b], 1u); break; }
            }
        }
    }
    __syncthreads();
    if (tid < NBINS) {
        if (swn[tid] != 0.0f) atomicAdd(&gz.wnum[tid], (double)swn[tid]);
        if (sct[tid])         atomicAdd(&gz.cnt[tid], sct[tid]);
    }
}

__global__ void k_ce(int ns, int nt) {
    int b = threadIdx.x;
    if (b < NBINS) {
        long long ct = (long long)gz.cnt[b];
        long long d  = ct - 1; if (d < 1) d = 1;
        double normal = (double)(nt - 1) / (double)ns;
        g_ce[b]    = (float)(normal * gz.wnum[b] / (double)d);
        g_cntok[b] = (ct > 1) ? 1 : 0;
    }
}

// Sum of (conf_t - cond_expect[bin])^2 over binned target samples.
__global__ void k_diff(int nt) {
    float e[16]; float ce[NBINS]; bool ok[NBINS];
#pragma unroll
    for (int k = 0; k < 16; k++) e[k] = g_edges[k];
#pragma unroll
    for (int k = 0; k < NBINS; k++) { ce[k] = g_ce[k]; ok[k] = (g_cntok[k] != 0); }
    int tid = threadIdx.x;
    double local = 0.0;
    int stride = gridDim.x * blockDim.x;
    for (int i = blockIdx.x * blockDim.x + tid; i < nt; i += stride) {
        float c = g_conf_t[i];
        if (c > e[0] && c <= e[15]) {
#pragma unroll
            for (int b = 0; b < NBINS; b++)
                if (c <= e[b + 1]) {
                    if (ok[b]) { float d = c - ce[b]; local += (double)d * (double)d; }
                    break;
                }
        }
    }
#pragma unroll
    for (int o = 16; o; o >>= 1) local += __shfl_down_sync(0xffffffffu, local, o);
    __shared__ double warpsum[8];
    if ((tid & 31) == 0) warpsum[tid >> 5] = local;
    __syncthreads();
    if (tid < 8) {
        double v = warpsum[tid];
#pragma unroll
        for (int o = 4; o; o >>= 1) v += __shfl_down_sync(0xffu, v, o);
        if (tid == 0) atomicAdd(&gz.total, v);
    }
}

__global__ void k_final(float* out, int nt) {
    out[0] = (float)(gz.total / (double)nt);
}

extern "C" void kernel_launch(void* const* d_in, const int* in_sizes, int n_in,
                              void* d_out, int out_size) {
    const float* lg_s = (const float*)d_in[0];
    const void*  lab  = d_in[1];
    const float* lg_t = (const float*)d_in[2];
    const float* wt   = (const float*)d_in[3];
    int ns = in_sizes[0] / NC;
    int nt = in_sizes[2] / NC;

    void* zp = nullptr;
    cudaGetSymbolAddress(&zp, gz);
    cudaMemsetAsync(zp, 0, sizeof(ZeroBlock), 0);

    k_detect<<<1, 32>>>((const unsigned*)lab);

    const int WPB = 8;  // 8 warps/block, one warp per row
    int rows = nt + ns;
    int blocks = (rows + WPB - 1) / WPB;
    k_conf<<<blocks, 256>>>(lg_t, lg_s, lab, wt, nt, ns);

    k_csum<<<NCHUNK, 256>>>();
    k_rank<<<NRANK, 1024>>>(nt);
    k_refine<<<888, 256>>>(nt);
    k_select<<<NRANK, 1024>>>(nt);
    k_edges<<<1, 32>>>(nt);
    k_binacc<<<1184, 256>>>(ns, nt, 592);
    k_ce<<<1, 32>>>(ns, nt);
    k_diff<<<888, 256>>>(nt);
    k_final<<<1, 1>>>((float*)d_out, nt);
    (void)n_in; (void)out_size;
}

// round 11
// speedup vs baseline: 1.4065x; 1.0215x over previous
#include <cuda_runtime.h>
#include <math.h>
#include <float.h>

// ---------------------------------------------------------------------------
// EceLabelShift: equal-mass-bin ECE with label-shift weighting.
//   conf = max softmax prob  (= 1/sum(exp(l - max)))
//   edges = equal-mass quantiles of conf_target (exact order statistics via
//           2-level radix histogram on the positive-float bit pattern)
//   per-bin: weighted source accuracy -> cond_expect; sum (conf_t - ce)^2
// R9: parallelized rank/select (block scans), parallel detect, fused +
//     vectorized softmax pass (float4 + ballot argmax).
// ---------------------------------------------------------------------------

#define NC      100
#define NBINS   15
#define HSIZE   (1 << 18)            // conf in (0,1] -> bits>>12 < 0x40000
#define CHUNK   1024
#define NCHUNK  (HSIZE / CHUNK)      // 256
#define NRANK   32                   // 16 edges x (i, i+1) rank pairs
#define NMAX    500000

struct ZeroBlock {
    unsigned hist[HSIZE];
    unsigned subhist[NRANK * 4096];
    double   wnum[NBINS];
    double   total;
    unsigned cnt[NBINS];
};
__device__ ZeroBlock gz;

__device__ float    g_conf_t[NMAX];
__device__ float    g_conf_s[NMAX];
__device__ float    g_wper[NMAX];
__device__ unsigned g_csum[NCHUNK];
__device__ int      g_rankBin[NRANK];
__device__ unsigned g_rankBase[NRANK];
__device__ float    g_srt[NRANK];
__device__ float    g_edges[16];
__device__ float    g_ce[NBINS];
__device__ unsigned char g_cntok[NBINS];
__device__ int      g_lab64;

// rank (0-indexed order statistic) needed for edge pair t: (i, i+1), clamped.
__device__ __forceinline__ long long rank_for(int t, int nt) {
    int k = t >> 1;
    double xq = (double)k * (double)nt / 15.0;
    long long i = (long long)floor(xq);
    if (i > (long long)nt - 1) i = (long long)nt - 1;
    long long r = i + (t & 1);
    if (r > (long long)nt - 1) r = (long long)nt - 1;
    return r;
}

// Block-wide (1024 thr = 32 warps) inclusive scan of one unsigned per thread.
__device__ __forceinline__ unsigned blockScanIncl(unsigned v, unsigned* sh) {
    int tid = threadIdx.x, lane = tid & 31, w = tid >> 5;
    unsigned sc = v;
#pragma unroll
    for (int o = 1; o < 32; o <<= 1) {
        unsigned u = __shfl_up_sync(0xffffffffu, sc, o);
        if (lane >= o) sc += u;
    }
    if (lane == 31) sh[w] = sc;
    __syncthreads();
    if (w == 0) {
        unsigned t = sh[lane];
#pragma unroll
        for (int o = 1; o < 32; o <<= 1) {
            unsigned u = __shfl_up_sync(0xffffffffu, t, o);
            if (lane >= o) t += u;
        }
        sh[lane] = t;
    }
    __syncthreads();
    unsigned off = w ? sh[w - 1] : 0u;
    return sc + off;
}

// Detect labels dtype: int64 => odd 32-bit words of first 64 entries are 0.
__global__ void k_detect(const unsigned* __restrict__ lab) {
    int t = threadIdx.x;                       // 32 threads
    unsigned v = lab[2 * t + 1] | lab[2 * t + 65];
    unsigned mask = __ballot_sync(0xffffffffu, v != 0u);
    if (t == 0) g_lab64 = (mask == 0u) ? 1 : 0;
}

// Fused conf pass: one warp per row for target (rows [0,nt)) and source rows.
__global__ void k_conf(const float* __restrict__ lg_t, const float* __restrict__ lg_s,
                       const void* __restrict__ labels, const float* __restrict__ wt,
                       int nt, int ns) {
    int gw   = (blockIdx.x * blockDim.x + threadIdx.x) >> 5;
    int lane = threadIdx.x & 31;
    if (gw >= nt + ns) return;
    bool isT = gw < nt;
    int row  = isT ? gw : gw - nt;
    const float* base = isT ? lg_t : lg_s;
    const float4* p = (const float4*)(base + (size_t)row * NC);  // 400B rows: 16B aligned
    float4 v;
    if (lane < 25) v = p[lane];
    else           v = make_float4(-FLT_MAX, -FLT_MAX, -FLT_MAX, -FLT_MAX);

    float m = fmaxf(fmaxf(v.x, v.y), fmaxf(v.z, v.w));
#pragma unroll
    for (int o = 16; o; o >>= 1) m = fmaxf(m, __shfl_xor_sync(0xffffffffu, m, o));

    float s = 0.0f;
    if (lane < 25)
        s = __expf(v.x - m) + __expf(v.y - m) + __expf(v.z - m) + __expf(v.w - m);
#pragma unroll
    for (int o = 16; o; o >>= 1) s += __shfl_xor_sync(0xffffffffu, s, o);

    if (isT) {
        if (lane == 0) {
            float c = 1.0f / s;
            g_conf_t[row] = c;
            atomicAdd(&gz.hist[__float_as_uint(c) >> 12], 1u);
        }
    } else {
        // argmax (first occurrence): find smallest index whose value == m
        int loc = 127;
        if (lane < 25) {
            if (v.w == m) loc = 4 * lane + 3;
            if (v.z == m) loc = 4 * lane + 2;
            if (v.y == m) loc = 4 * lane + 1;
            if (v.x == m) loc = 4 * lane;
        }
        unsigned mask = __ballot_sync(0xffffffffu, loc < 127);
        int src = __ffs(mask) - 1;
        int bi  = __shfl_sync(0xffffffffu, loc, src);
        if (lane == 0) {
            g_conf_s[row] = 1.0f / s;
            long long lab = g_lab64 ? ((const long long*)labels)[row]
                                    : (long long)((const int*)labels)[row];
            g_wper[row] = (bi == (int)lab) ? wt[lab] : 0.0f;
        }
    }
}

// Per-chunk sums of the coarse histogram (grid = NCHUNK blocks).
__global__ void k_csum() {
    int c = blockIdx.x, tid = threadIdx.x;   // 256 threads
    unsigned s = 0;
#pragma unroll
    for (int j = 0; j < CHUNK / 256; j++) s += gz.hist[c * CHUNK + j * 256 + tid];
#pragma unroll
    for (int o = 16; o; o >>= 1) s += __shfl_xor_sync(0xffffffffu, s, o);
    __shared__ unsigned ws[8];
    if ((tid & 31) == 0) ws[tid >> 5] = s;
    __syncthreads();
    if (tid < 8) {
        unsigned v = ws[tid];
#pragma unroll
        for (int o = 4; o; o >>= 1) v += __shfl_xor_sync(0xffu, v, o);
        if (tid == 0) g_csum[c] = v;
    }
}

// One block per rank: prefix over chunk sums, locate chunk, block-scan chunk.
__global__ void k_rank(int nt) {
    __shared__ unsigned cpref[NCHUNK + 1];
    __shared__ unsigned sh[32];
    __shared__ int cIdx;
    __shared__ int firstIdx;
    int tid = threadIdx.x, b = blockIdx.x;
    if (tid == 0) firstIdx = 1 << 30;
    if (tid < 32) {
        unsigned s[8]; unsigned run = 0;
#pragma unroll
        for (int j = 0; j < 8; j++) { unsigned h = g_csum[tid * 8 + j]; s[j] = run; run += h; }
        unsigned sc = run;
#pragma unroll
        for (int o = 1; o < 32; o <<= 1) {
            unsigned u = __shfl_up_sync(0xffffffffu, sc, o);
            if (tid >= o) sc += u;
        }
        unsigned excl = sc - run;
#pragma unroll
        for (int j = 0; j < 8; j++) cpref[tid * 8 + j] = excl + s[j];
        if (tid == 31) cpref[NCHUNK] = excl + run;
    }
    __syncthreads();
    unsigned r = (unsigned)rank_for(b, nt);
    if (tid < NCHUNK && cpref[tid] <= r && r < cpref[tid + 1]) cIdx = tid;
    __syncthreads();
    int c = cIdx;
    unsigned h = gz.hist[c * CHUNK + tid];
    unsigned incl = blockScanIncl(h, sh);
    unsigned cum0 = cpref[c];
    if (cum0 + incl > r) atomicMin(&firstIdx, tid);
    __syncthreads();
    if (tid == firstIdx) {
        g_rankBin[b]  = c * CHUNK + tid;
        g_rankBase[b] = cum0 + incl - h;
    }
}

// Sub-histogram (low 12 key bits) for each rank's coarse bin.
__global__ void k_refine(int nt) {
    __shared__ int sb[NRANK];
    if (threadIdx.x < NRANK) sb[threadIdx.x] = g_rankBin[threadIdx.x];
    __syncthreads();
    int myb[NRANK];
    int bmin = 0x7fffffff, bmax = -1;
#pragma unroll
    for (int t = 0; t < NRANK; t++) {
        myb[t] = sb[t];
        bmin = min(bmin, myb[t]); bmax = max(bmax, myb[t]);
    }
    int stride = gridDim.x * blockDim.x;
    for (int i = blockIdx.x * blockDim.x + threadIdx.x; i < nt; i += stride) {
        unsigned key = __float_as_uint(g_conf_t[i]);
        int bbin = (int)(key >> 12);
        if (bbin < bmin || bbin > bmax) continue;
        unsigned low = key & 4095u;
#pragma unroll
        for (int t = 0; t < NRANK; t++)
            if (myb[t] == bbin) atomicAdd(&gz.subhist[t * 4096 + low], 1u);
    }
}

// One block per rank: block scan of its 4096-bin sub-hist -> exact float.
__global__ void k_select(int nt) {
    __shared__ unsigned sh[32];
    __shared__ int firstIdx;
    int tid = threadIdx.x, b = blockIdx.x;
    if (tid == 0) firstIdx = 1 << 30;
    unsigned target = (unsigned)(rank_for(b, nt) - (long long)g_rankBase[b]);
    unsigned h[4]; unsigned tsum = 0;
    int base = b * 4096 + tid * 4;
#pragma unroll
    for (int j = 0; j < 4; j++) { h[j] = gz.subhist[base + j]; tsum += h[j]; }
    unsigned incl = blockScanIncl(tsum, sh);
    unsigned cum  = incl - tsum;
    int found = -1;
#pragma unroll
    for (int j = 0; j < 4; j++) {
        if (found < 0 && cum + h[j] > target) found = tid * 4 + j;
        cum += h[j];
    }
    if (found >= 0) atomicMin(&firstIdx, found);
    __syncthreads();
    if (tid == 0)
        g_srt[b] = __uint_as_float(((unsigned)g_rankBin[b] << 12) | (unsigned)firstIdx);
}

// Interpolate the 16 equal-mass edges from the 32 order statistics.
__global__ void k_edges(int nt) {
    int k = threadIdx.x;
    if (k < 16) {
        float e;
        if (k == 0)       e = g_srt[0];
        else if (k == 15) e = g_srt[31];
        else {
            double xq = (double)k * (double)nt / 15.0;
            long long i = (long long)floor(xq);
            double frac = xq - (double)i;
            double a = g_srt[2 * k], b2 = g_srt[2 * k + 1];
            e = (float)(a + frac * (b2 - a));
        }
        g_edges[k] = e;
    }
}

// Bin accumulation: blocks [0,srcBlocks) -> weighted_num, rest -> count_t.
__global__ void k_binacc(int ns, int nt, int srcBlocks) {
    __shared__ float    swn[NBINS];
    __shared__ unsigned sct[NBINS];
    int tid = threadIdx.x;
    if (tid < NBINS) { swn[tid] = 0.0f; sct[tid] = 0u; }
    float e[16];
#pragma unroll
    for (int k = 0; k < 16; k++) e[k] = g_edges[k];
    __syncthreads();
    if ((int)blockIdx.x < srcBlocks) {
        int stride = srcBlocks * blockDim.x;
        for (int i = blockIdx.x * blockDim.x + tid; i < ns; i += stride) {
            float w = g_wper[i];
            if (w != 0.0f) {
                float c = g_conf_s[i];
                if (c > e[0] && c <= e[15]) {
#pragma unroll
                    for (int b = 0; b < NBINS; b++)
                        if (c <= e[b + 1]) { atomicAdd(&swn[b], w); break; }
                }
            }
        }
    } else {
        int nb = gridDim.x - srcBlocks;
        int stride = nb * blockDim.x;
        for (int i = ((int)blockIdx.x - srcBlocks) * blockDim.x + tid; i < nt; i += stride) {
            float c = g_conf_t[i];
            if (c > e[0] && c <= e[15]) {
#pragma unroll
                for (int b = 0; b < NBINS; b++)
                    if (c <= e[b + 1]) { atomicAdd(&sct[b], 1u); break; }
            }
        }
    }
    __syncthreads();
    if (tid < NBINS) {
        if (swn[tid] != 0.0f) atomicAdd(&gz.wnum[tid], (double)swn[tid]);
        if (sct[tid])         atomicAdd(&gz.cnt[tid], sct[tid]);
    }
}

__global__ void k_ce(int ns, int nt) {
    int b = threadIdx.x;
    if (b < NBINS) {
        long long ct = (long long)gz.cnt[b];
        long long d  = ct - 1; if (d < 1) d = 1;
        double normal = (double)(nt - 1) / (double)ns;
        g_ce[b]    = (float)(normal * gz.wnum[b] / (double)d);
        g_cntok[b] = (ct > 1) ? 1 : 0;
    }
}

// Sum of (conf_t - cond_expect[bin])^2 over binned target samples.
__global__ void k_diff(int nt) {
    float e[16]; float ce[NBINS]; bool ok[NBINS];
#pragma unroll
    for (int k = 0; k < 16; k++) e[k] = g_edges[k];
#pragma unroll
    for (int k = 0; k < NBINS; k++) { ce[k] = g_ce[k]; ok[k] = (g_cntok[k] != 0); }
    int tid = threadIdx.x;
    double local = 0.0;
    int stride = gridDim.x * blockDim.x;
    for (int i = blockIdx.x * blockDim.x + tid; i < nt; i += stride) {
        float c = g_conf_t[i];
        if (c > e[0] && c <= e[15]) {
#pragma unroll
            for (int b = 0; b < NBINS; b++)
                if (c <= e[b + 1]) {
                    if (ok[b]) { float d = c - ce[b]; local += (double)d * (double)d; }
                    break;
                }
        }
    }
#pragma unroll
    for (int o = 16; o; o >>= 1) local += __shfl_down_sync(0xffffffffu, local, o);
    __shared__ double warpsum[8];
    if ((tid & 31) == 0) warpsum[tid >> 5] = local;
    __syncthreads();
    if (tid < 8) {
        double v = warpsum[tid];
#pragma unroll
        for (int o = 4; o; o >>= 1) v += __shfl_down_sync(0xffu, v, o);
        if (tid == 0) atomicAdd(&gz.total, v);
    }
}

__global__ void k_final(float* out, int nt) {
    out[0] = (float)(gz.total / (double)nt);
}

extern "C" void kernel_launch(void* const* d_in, const int* in_sizes, int n_in,
                              void* d_out, int out_size) {
    const float* lg_s = (const float*)d_in[0];
    const void*  lab  = d_in[1];
    const float* lg_t = (const float*)d_in[2];
    const float* wt   = (const float*)d_in[3];
    int ns = in_sizes[0] / NC;
    int nt = in_sizes[2] / NC;

    void* zp = nullptr;
    cudaGetSymbolAddress(&zp, gz);
    cudaMemsetAsync(zp, 0, sizeof(ZeroBlock), 0);

    k_detect<<<1, 32>>>((const unsigned*)lab);

    const int WPB = 8;  // 8 warps/block, one warp per row
    int rows = nt + ns;
    int blocks = (rows + WPB - 1) / WPB;
    k_conf<<<blocks, 256>>>(lg_t, lg_s, lab, wt, nt, ns);

    k_csum<<<NCHUNK, 256>>>();
    k_rank<<<NRANK, 1024>>>(nt);
    k_refine<<<888, 256>>>(nt);
    k_select<<<NRANK, 1024>>>(nt);
    k_edges<<<1, 32>>>(nt);
    k_binacc<<<1184, 256>>>(ns, nt, 592);
    k_ce<<<1, 32>>>(ns, nt);
    k_diff<<<888, 256>>>(nt);
    k_final<<<1, 1>>>((float*)d_out, nt);
    (void)n_in; (void)out_size;
}